// round 4
// baseline (speedup 1.0000x reference)
#include <cuda_runtime.h>
#include <math.h>

#define NANC   10647
#define NBOX   50
#define BATCH  32
#define NCLS   20
#define NUMNEG 1000

// ---------------- scratch (static device globals: no runtime allocation) ----------------
__device__ float4             g_pltrb[BATCH * NANC];   // decoded pred boxes (ltrb)
__device__ unsigned long long g_keys [BATCH * NANC];   // (ordered(masked)<<32)|anchor
__device__ float              g_neg  [BATCH];          // per-image l_conf_neg
__device__ float              g_pos  [BATCH * NBOX];   // per-(image,box) cls+iou+conf_pos

// ---------------- constants ----------------
__constant__ float c_asc_x[9] = {10.f/416.f,16.f/416.f,33.f/416.f,30.f/416.f,62.f/416.f,
                                 59.f/416.f,116.f/416.f,156.f/416.f,373.f/416.f};
__constant__ float c_asc_y[9] = {13.f/416.f,30.f/416.f,23.f/416.f,61.f/416.f,45.f/416.f,
                                 119.f/416.f,90.f/416.f,198.f/416.f,326.f/416.f};
__constant__ float c_fs9[9]   = {52.f,52.f,52.f,26.f,26.f,26.f,13.f,13.f,13.f};
__constant__ int   c_cum[3]   = {0, 2704, 3380};
__constant__ int   c_fsl[3]   = {52, 26, 13};

// ---------------- math helpers ----------------
// CIoU with per-operand precomputables: l,t,r,b, area, atan(w/(h+eps)), sx=l+r, sy=t+b
__device__ __forceinline__ float ciou_pre(float l1,float t1,float r1,float b1,
                                          float area1,float at1,float sx1,float sy1,
                                          float l2,float t2,float r2,float b2,
                                          float area2,float at2,float sx2,float sy2)
{
    const float eps = 1e-7f;
    float iw = fminf(r1,r2) - fmaxf(l1,l2); iw = fmaxf(iw, 0.f);
    float ih = fminf(b1,b2) - fmaxf(t1,t2); ih = fmaxf(ih, 0.f);
    float inter = iw * ih;
    float uni   = area1 + area2 - inter + eps;
    float iou   = __fdividef(inter, uni);
    float cw = fmaxf(r1,r2) - fminf(l1,l2);
    float ch = fmaxf(b1,b2) - fminf(t1,t2);
    float c2 = cw*cw + ch*ch + eps;
    float dx = sx1 - sx2;
    float dy = sy1 - sy2;
    float rho2 = (dx*dx + dy*dy) * 0.25f;
    float dd = at1 - at2;
    float v  = 0.40528473456935109f * dd * dd;      // 4/pi^2
    float alpha = __fdividef(v, (1.f - iou) + v + eps);
    return iou - __fdividef(rho2, c2) - alpha * v;
}

__device__ __forceinline__ float softplusf(float x){           // log(1+e^x), stable
    return fmaxf(x, 0.f) + log1pf(expf(-fabsf(x)));
}
__device__ __forceinline__ float sigmf(float x){ return 1.f / (1.f + expf(-x)); }
__device__ __forceinline__ float focal0(float x){              // target 0
    float s = sigmf(x); return softplusf(x) * 0.75f * s * s;
}
__device__ __forceinline__ float focal1(float x){              // target 1
    float s = sigmf(x); float o = 1.f - s;
    return (softplusf(x) - x) * 0.25f * o * o;
}
__device__ __forceinline__ unsigned ordf(float f){             // order-preserving float->uint
    unsigned u = __float_as_uint(f);
    return (u & 0x80000000u) ? ~u : (u | 0x80000000u);
}
__device__ __forceinline__ float fs_of(int a){
    return (a < 8112) ? 52.f : ((a < 10140) ? 26.f : 13.f);
}

// anchor-side registers for the pair loop
struct AncReg {
    float l, t, r, b, area, at, sx, sy;
};

__device__ __forceinline__ AncReg decode_anchor(const float* __restrict__ p,
                                                const float* __restrict__ ancs,
                                                int b, int a)
{
    const float* pp = p + ((size_t)b * NANC + a) * 25;
    float4 an = ((const float4*)ancs)[a];
    float fs = fs_of(a);
    float cx = (1.f / (1.f + expf(-pp[0]))) / fs + an.x;
    float cy = (1.f / (1.f + expf(-pp[1]))) / fs + an.y;
    float w  = expf(pp[2]) * an.z;
    float h  = expf(pp[3]) * an.w;
    AncReg R;
    R.l = cx - w * 0.5f; R.t = cy - h * 0.5f;
    R.r = cx + w * 0.5f; R.b = cy + h * 0.5f;
    g_pltrb[b * NANC + a] = make_float4(R.l, R.t, R.r, R.b);
    float w2 = R.r - R.l, h2 = R.b - R.t;
    R.area = w2 * h2;
    R.at   = atanf(w2 / (h2 + 1e-7f));
    R.sx   = R.l + R.r;
    R.sy   = R.t + R.b;
    return R;
}

// ---------------- K1: decode + per-anchor max CIoU over boxes + OHEM keys (2 anchors/thread) ----
__global__ void k_decode(const float* __restrict__ p, const float* __restrict__ boxes,
                         const float* __restrict__ ancs)
{
    __shared__ float4 sA[NBOX];   // l,t,r,b
    __shared__ float4 sB[NBOX];   // area, atan, sx=l+r, sy=t+b
    const int b = blockIdx.y;
    const int t = threadIdx.x;
    if (t < NBOX) {
        float4 bx = ((const float4*)boxes)[b * NBOX + t];
        sA[t] = bx;
        float w = bx.z - bx.x, h = bx.w - bx.y;
        sB[t] = make_float4(w * h, atanf(w / (h + 1e-7f)), bx.x + bx.z, bx.y + bx.w);
    }
    __syncthreads();

    int a0 = (blockIdx.x * blockDim.x + t) * 2;
    if (a0 >= NANC) return;
    const int  a1   = a0 + 1;
    const bool has1 = (a1 < NANC);

    AncReg X = decode_anchor(p, ancs, b, a0);
    AncReg Y = has1 ? decode_anchor(p, ancs, b, a1) : X;

    float mx0 = -1e30f, mx1 = -1e30f;
    #pragma unroll 2
    for (int i = 0; i < NBOX; i++) {
        float4 A  = sA[i];
        float4 Bb = sB[i];
        mx0 = fmaxf(mx0, ciou_pre(A.x, A.y, A.z, A.w, Bb.x, Bb.y, Bb.z, Bb.w,
                                  X.l, X.t, X.r, X.b, X.area, X.at, X.sx, X.sy));
        mx1 = fmaxf(mx1, ciou_pre(A.x, A.y, A.z, A.w, Bb.x, Bb.y, Bb.z, Bb.w,
                                  Y.l, Y.t, Y.r, Y.b, Y.area, Y.at, Y.sx, Y.sy));
    }
    float m0 = (mx0 < 0.5f) ? mx0 : __int_as_float(0x7f800000);  // +inf
    g_keys[b * NANC + a0] = (((unsigned long long)ordf(m0)) << 32) | (unsigned)a0;
    if (has1) {
        float m1 = (mx1 < 0.5f) ? mx1 : __int_as_float(0x7f800000);
        g_keys[b * NANC + a1] = (((unsigned long long)ordf(m1)) << 32) | (unsigned)a1;
    }
}

// ---------------- K2: per-image exact 1000-smallest radix-select + negative focal ----------------
__global__ void k_select(const float* __restrict__ p)
{
    extern __shared__ unsigned long long sk[];          // NANC keys (85 KB)
    __shared__ unsigned hist[256];
    __shared__ unsigned long long s_pref;
    __shared__ int s_k;
    __shared__ float s_red[32];

    const int b = blockIdx.x, t = threadIdx.x;
    for (int i = t; i < NANC; i += blockDim.x) sk[i] = g_keys[b * NANC + i];
    __syncthreads();

    unsigned long long prefix = 0ull, pmask = 0ull;
    int k = NUMNEG;                                     // 1-indexed rank of target key
    for (int shift = 56; shift >= 0; shift -= 8) {
        if (t < 256) hist[t] = 0u;
        __syncthreads();
        for (int i = t; i < NANC; i += blockDim.x) {
            unsigned long long e = sk[i];
            if ((e & pmask) == prefix)
                atomicAdd(&hist[(unsigned)(e >> shift) & 255u], 1u);
        }
        __syncthreads();
        if (t == 0) {
            int run = 0, d = 0;
            for (; d < 255; d++) {
                int c = (int)hist[d];
                if (run + c >= k) break;
                run += c;
            }
            s_pref = prefix | ((unsigned long long)d << shift);
            s_k    = k - run;
        }
        __syncthreads();
        prefix = s_pref; k = s_k;
        pmask |= (0xFFull << shift);
        __syncthreads();
    }
    // keys are unique -> exactly NUMNEG keys satisfy key <= prefix (the kth-smallest)
    float sum = 0.f;
    for (int i = t; i < NANC; i += blockDim.x) {
        unsigned long long e = sk[i];
        if (e <= prefix) {
            int idx = (int)(unsigned)(e & 0xffffffffu);
            sum += focal0(p[((size_t)b * NANC + idx) * 25 + 4]);
        }
    }
    for (int o = 16; o > 0; o >>= 1) sum += __shfl_xor_sync(0xffffffffu, sum, o);
    if ((t & 31) == 0) s_red[t >> 5] = sum;
    __syncthreads();
    if (t < 32) {
        float v = (t < (int)(blockDim.x >> 5)) ? s_red[t] : 0.f;
        for (int o = 16; o > 0; o >>= 1) v += __shfl_xor_sync(0xffffffffu, v, o);
        if (t == 0) g_neg[b] = v;
    }
}

// ---------------- K3: anchor matching (with offset trick) + positive losses ----------------
__global__ void k_pos(const float* __restrict__ p, const float* __restrict__ boxes,
                      const int* __restrict__ labels)
{
    __shared__ float sl[NBOX], st[NBOX], sr[NBOX], sbb[NBOX], scx[NBOX], scy[NBOX];
    __shared__ float rv[128];
    __shared__ int   ri[128];
    const int b = blockIdx.y, i = blockIdx.x, t = threadIdx.x;
    if (t < NBOX) {
        float4 bx = ((const float4*)boxes)[b * NBOX + t];
        sl[t] = bx.x; st[t] = bx.y; sr[t] = bx.z; sbb[t] = bx.w;
        scx[t] = (bx.x + bx.z) * 0.5f;
        scy[t] = (bx.y + bx.w) * 0.5f;
    }
    __syncthreads();

    float l1 = sl[i], t1 = st[i], r1 = sr[i], b1 = sbb[i];
    float w1 = r1 - l1, h1 = b1 - t1;
    float area1 = w1 * h1;
    float at1   = atanf(w1 / (h1 + 1e-7f));
    float off1  = (float)i;
    float l1o = l1 + off1, t1o = t1 + off1, r1o = r1 + off1, b1o = b1 + off1;

    float best = -1e30f; int bestj = 1 << 30;
    for (int j = t; j < NBOX * 9; j += blockDim.x) {
        int jb = j / 9, a9 = j - jb * 9;
        float f = c_fs9[a9];
        float acx = floorf(scx[jb] * f) / f;
        float acy = floorf(scy[jb] * f) / f;
        float aw = c_asc_x[a9], ah = c_asc_y[a9];
        float offj = (float)jb;
        float l2 = acx - aw * 0.5f + offj, t2 = acy - ah * 0.5f + offj;
        float r2 = acx + aw * 0.5f + offj, b2 = acy + ah * 0.5f + offj;
        float w2 = r2 - l2, h2 = b2 - t2;
        float v = ciou_pre(l1o, t1o, r1o, b1o, area1, at1, l1o + r1o, t1o + b1o,
                           l2, t2, r2, b2, w2 * h2, atanf(w2 / (h2 + 1e-7f)),
                           l2 + r2, t2 + b2);
        if (v > best) { best = v; bestj = j; }      // ascending j -> first max within thread
    }
    rv[t] = best; ri[t] = bestj;
    __syncthreads();
    for (int s = 64; s > 0; s >>= 1) {
        if (t < s) {
            if (rv[t + s] > rv[t] || (rv[t + s] == rv[t] && ri[t + s] < ri[t])) {
                rv[t] = rv[t + s]; ri[t] = ri[t + s];
            }
        }
        __syncthreads();
    }
    if (t == 0) {
        int k   = ri[0] % 9;
        int lev = k / 3;
        float ff = c_fs9[k];
        int col = (int)floorf(scx[i] * ff);
        int row = (int)floorf(scy[i] * ff);
        int fin = c_fsl[lev];
        int midx = (c_cum[lev] + row * fin + col) * 3 + lev;

        const float* pm = p + ((size_t)b * NANC + midx) * 25;
        float acc = focal1(pm[4]);                                  // l_conf_pos
        int lab = labels[b * NBOX + i] - 1;
        #pragma unroll
        for (int c = 0; c < NCLS; c++) {                            // l_cls: bce = softplus(x) - t*x
            float x = pm[5 + c];
            acc += softplusf(x) - ((c == lab) ? x : 0.f);
        }
        float4 pl = g_pltrb[b * NANC + midx];                       // l_iou
        float wp = pl.z - pl.x, hp = pl.w - pl.y;
        float iou1 = ciou_pre(l1, t1, r1, b1, area1, at1, l1 + r1, t1 + b1,
                              pl.x, pl.y, pl.z, pl.w, wp * hp, atanf(wp / (hp + 1e-7f)),
                              pl.x + pl.z, pl.y + pl.w);
        acc += (2.f - area1) * (1.f - iou1);
        g_pos[b * NBOX + i] = acc;
    }
}

// ---------------- K4: deterministic fixed-tree final reduction ----------------
__global__ void k_final(float* __restrict__ out)
{
    __shared__ double sd[512];
    const int t = threadIdx.x;
    double v = 0.0;
    for (int i = t; i < BATCH; i += 512)
        v += (double)g_neg[i] * (1.0 / BATCH);
    for (int i = t; i < BATCH * NBOX; i += 512)
        v += (double)g_pos[i] * (1.0 / (BATCH * NBOX));
    sd[t] = v;
    __syncthreads();
    for (int s = 256; s > 0; s >>= 1) {
        if (t < s) sd[t] += sd[t + s];
        __syncthreads();
    }
    if (t == 0) out[0] = (float)sd[0];
}

// ---------------- launch ----------------
extern "C" void kernel_launch(void* const* d_in, const int* in_sizes, int n_in,
                              void* d_out, int out_size)
{
    const float* p      = (const float*)d_in[0];
    const float* boxes  = (const float*)d_in[1];
    const int*   labels = (const int*)  d_in[2];
    const float* ancs   = (const float*)d_in[3];
    float*       out    = (float*)d_out;

    cudaFuncSetAttribute(k_select, cudaFuncAttributeMaxDynamicSharedMemorySize,
                         (int)(NANC * sizeof(unsigned long long)));

    const int pairs = (NANC + 1) / 2;                     // 2 anchors per thread
    dim3 g1((pairs + 255) / 256, BATCH);
    k_decode<<<g1, 256>>>(p, boxes, ancs);
    k_select<<<BATCH, 1024, NANC * sizeof(unsigned long long)>>>(p);
    dim3 g3(NBOX, BATCH);
    k_pos<<<g3, 128>>>(p, boxes, labels);
    k_final<<<1, 512>>>(out);
}

// round 5
// speedup vs baseline: 1.8809x; 1.8809x over previous
#include <cuda_runtime.h>
#include <math.h>

#define NANC   10647
#define NBOX   50
#define BATCH  32
#define NCLS   20
#define NUMNEG 1000

// ---------------- scratch (static device globals: no runtime allocation) ----------------
__device__ float4             g_pltrb[BATCH * NANC];   // decoded pred boxes (ltrb)
__device__ unsigned long long g_keys [BATCH * NANC];   // (ordered(masked)<<32)|anchor
__device__ float              g_neg  [BATCH];          // per-image l_conf_neg
__device__ __align__(16) float g_pos [BATCH * NBOX];   // per-(image,box) cls+iou+conf_pos

// ---------------- constants ----------------
__constant__ float c_asc_x[9] = {10.f/416.f,16.f/416.f,33.f/416.f,30.f/416.f,62.f/416.f,
                                 59.f/416.f,116.f/416.f,156.f/416.f,373.f/416.f};
__constant__ float c_asc_y[9] = {13.f/416.f,30.f/416.f,23.f/416.f,61.f/416.f,45.f/416.f,
                                 119.f/416.f,90.f/416.f,198.f/416.f,326.f/416.f};
__constant__ float c_fs9[9]   = {52.f,52.f,52.f,26.f,26.f,26.f,13.f,13.f,13.f};
__constant__ int   c_cum[3]   = {0, 2704, 3380};
__constant__ int   c_fsl[3]   = {52, 26, 13};

// ---------------- math helpers ----------------
__device__ __forceinline__ float ciou_pre(float l1,float t1,float r1,float b1,
                                          float area1,float at1,float sx1,float sy1,
                                          float l2,float t2,float r2,float b2,
                                          float area2,float at2,float sx2,float sy2)
{
    const float eps = 1e-7f;
    float iw = fminf(r1,r2) - fmaxf(l1,l2); iw = fmaxf(iw, 0.f);
    float ih = fminf(b1,b2) - fmaxf(t1,t2); ih = fmaxf(ih, 0.f);
    float inter = iw * ih;
    float uni   = area1 + area2 - inter + eps;
    float iou   = __fdividef(inter, uni);
    float cw = fmaxf(r1,r2) - fminf(l1,l2);
    float ch = fmaxf(b1,b2) - fminf(t1,t2);
    float c2 = cw*cw + ch*ch + eps;
    float dx = sx1 - sx2;
    float dy = sy1 - sy2;
    float rho2 = (dx*dx + dy*dy) * 0.25f;
    float dd = at1 - at2;
    float v  = 0.40528473456935109f * dd * dd;      // 4/pi^2
    float alpha = __fdividef(v, (1.f - iou) + v + eps);
    return iou - __fdividef(rho2, c2) - alpha * v;
}

__device__ __forceinline__ float softplusf(float x){
    return fmaxf(x, 0.f) + log1pf(expf(-fabsf(x)));
}
__device__ __forceinline__ float sigmf(float x){ return 1.f / (1.f + expf(-x)); }
__device__ __forceinline__ float focal0(float x){
    float s = sigmf(x); return softplusf(x) * 0.75f * s * s;
}
__device__ __forceinline__ float focal1(float x){
    float s = sigmf(x); float o = 1.f - s;
    return (softplusf(x) - x) * 0.25f * o * o;
}
__device__ __forceinline__ unsigned ordf(float f){
    unsigned u = __float_as_uint(f);
    return (u & 0x80000000u) ? ~u : (u | 0x80000000u);
}
__device__ __forceinline__ float fs_of(int a){
    return (a < 8112) ? 52.f : ((a < 10140) ? 26.f : 13.f);
}

struct AncReg { float l, t, r, b, area, at, sx, sy; };

__device__ __forceinline__ AncReg decode_anchor(const float* __restrict__ p,
                                                const float* __restrict__ ancs,
                                                int b, int a)
{
    const float* pp = p + ((size_t)b * NANC + a) * 25;
    float4 an = ((const float4*)ancs)[a];
    float fs = fs_of(a);
    float cx = (1.f / (1.f + expf(-pp[0]))) / fs + an.x;
    float cy = (1.f / (1.f + expf(-pp[1]))) / fs + an.y;
    float w  = expf(pp[2]) * an.z;
    float h  = expf(pp[3]) * an.w;
    AncReg R;
    R.l = cx - w * 0.5f; R.t = cy - h * 0.5f;
    R.r = cx + w * 0.5f; R.b = cy + h * 0.5f;
    g_pltrb[b * NANC + a] = make_float4(R.l, R.t, R.r, R.b);
    float w2 = R.r - R.l, h2 = R.b - R.t;
    R.area = w2 * h2;
    R.at   = atanf(w2 / (h2 + 1e-7f));
    R.sx   = R.l + R.r;
    R.sy   = R.t + R.b;
    return R;
}

// ---------------- K1: decode + per-anchor max CIoU over boxes + OHEM keys (2 anchors/thread) ----
__global__ void k_decode(const float* __restrict__ p, const float* __restrict__ boxes,
                         const float* __restrict__ ancs)
{
    __shared__ float4 sA[NBOX];
    __shared__ float4 sB[NBOX];
    const int b = blockIdx.y;
    const int t = threadIdx.x;
    if (t < NBOX) {
        float4 bx = ((const float4*)boxes)[b * NBOX + t];
        sA[t] = bx;
        float w = bx.z - bx.x, h = bx.w - bx.y;
        sB[t] = make_float4(w * h, atanf(w / (h + 1e-7f)), bx.x + bx.z, bx.y + bx.w);
    }
    __syncthreads();

    int a0 = (blockIdx.x * blockDim.x + t) * 2;
    if (a0 >= NANC) return;
    const int  a1   = a0 + 1;
    const bool has1 = (a1 < NANC);

    AncReg X = decode_anchor(p, ancs, b, a0);
    AncReg Y = has1 ? decode_anchor(p, ancs, b, a1) : X;

    float mx0 = -1e30f, mx1 = -1e30f;
    #pragma unroll 2
    for (int i = 0; i < NBOX; i++) {
        float4 A  = sA[i];
        float4 Bb = sB[i];
        mx0 = fmaxf(mx0, ciou_pre(A.x, A.y, A.z, A.w, Bb.x, Bb.y, Bb.z, Bb.w,
                                  X.l, X.t, X.r, X.b, X.area, X.at, X.sx, X.sy));
        mx1 = fmaxf(mx1, ciou_pre(A.x, A.y, A.z, A.w, Bb.x, Bb.y, Bb.z, Bb.w,
                                  Y.l, Y.t, Y.r, Y.b, Y.area, Y.at, Y.sx, Y.sy));
    }
    float m0 = (mx0 < 0.5f) ? mx0 : __int_as_float(0x7f800000);
    g_keys[b * NANC + a0] = (((unsigned long long)ordf(m0)) << 32) | (unsigned)a0;
    if (has1) {
        float m1 = (mx1 < 0.5f) ? mx1 : __int_as_float(0x7f800000);
        g_keys[b * NANC + a1] = (((unsigned long long)ordf(m1)) << 32) | (unsigned)a1;
    }
}

// ---------------- K2: 1000-smallest radix-select (6 passes, match-aggregated hist) ------------
// Key layout: [63:32]=ordered float, [31:14]=0, [13:0]=anchor index. Bytes 3,2 are always 0,
// so passes run at shifts {56,48,40,32,8,0}; the zero bytes are folded into the prefix mask.
__global__ void k_select(const float* __restrict__ p)
{
    extern __shared__ unsigned long long sk[];          // NANC keys (85 KB)
    __shared__ unsigned hist[256];
    __shared__ unsigned long long s_pref;
    __shared__ int s_k;
    __shared__ float s_red[32];

    const int b = blockIdx.x, t = threadIdx.x;
    const int lane = t & 31;
    for (int i = t; i < NANC; i += 1024) sk[i] = g_keys[b * NANC + i];
    __syncthreads();

    unsigned long long prefix = 0ull, pmask = 0ull;
    int k = NUMNEG;
    const int shifts[6] = {56, 48, 40, 32, 8, 0};

    #pragma unroll
    for (int pi = 0; pi < 6; pi++) {
        const int shift = shifts[pi];
        if (t < 256) hist[t] = 0u;
        __syncthreads();

        for (int base = 0; base < NANC; base += 1024) {
            int i = base + t;
            bool ok = false; unsigned digit = 0;
            if (i < NANC) {
                unsigned long long e = sk[i];
                ok = ((e & pmask) == prefix);
                digit = (unsigned)(e >> shift) & 255u;
            }
            unsigned bal = __ballot_sync(0xffffffffu, ok);
            if (ok) {
                unsigned same = __match_any_sync(bal, digit);   // lanes sharing this digit
                if (lane == (__ffs(same) - 1))                  // one leader per digit group
                    atomicAdd(&hist[digit], __popc(same));
            }
        }
        __syncthreads();

        // parallel scan over 256 bins by warp 0: find bin containing rank k
        if (t < 32) {
            int lo = t * 8;
            unsigned c[8]; int lsum = 0;
            #pragma unroll
            for (int j = 0; j < 8; j++) { c[j] = hist[lo + j]; lsum += (int)c[j]; }
            int pre = lsum;
            #pragma unroll
            for (int o = 1; o < 32; o <<= 1) {
                int n = __shfl_up_sync(0xffffffffu, pre, o);
                if (t >= o) pre += n;
            }
            int excl = pre - lsum;                       // count in bins before this lane's range
            if (excl < k && k <= excl + lsum) {          // exactly one lane true
                int run = excl, d = lo;
                #pragma unroll
                for (int j = 0; j < 8; j++) {
                    if (run + (int)c[j] >= k) { d = lo + j; break; }
                    run += (int)c[j];
                }
                s_pref = prefix | ((unsigned long long)(unsigned)d << shift);
                s_k    = k - run;
            }
        }
        __syncthreads();
        prefix = s_pref; k = s_k;
        pmask |= (0xFFull << shift);
        if (pi == 3) pmask |= (0xFFFFull << 16);         // bytes 3,2 are zero in every key
        __syncthreads();
    }

    // keys unique -> exactly NUMNEG keys satisfy key <= prefix (the kth-smallest key)
    float sum = 0.f;
    for (int i = t; i < NANC; i += 1024) {
        unsigned long long e = sk[i];
        if (e <= prefix) {
            int idx = (int)(unsigned)(e & 0xffffffffu);
            sum += focal0(p[((size_t)b * NANC + idx) * 25 + 4]);
        }
    }
    for (int o = 16; o > 0; o >>= 1) sum += __shfl_xor_sync(0xffffffffu, sum, o);
    if (lane == 0) s_red[t >> 5] = sum;
    __syncthreads();
    if (t < 32) {
        float v = (t < 32) ? s_red[t] : 0.f;
        for (int o = 16; o > 0; o >>= 1) v += __shfl_xor_sync(0xffffffffu, v, o);
        if (t == 0) g_neg[b] = v;
    }
}

// ---------------- K3: anchor matching (with offset trick) + positive losses ----------------
__global__ void k_pos(const float* __restrict__ p, const float* __restrict__ boxes,
                      const int* __restrict__ labels)
{
    __shared__ float sl[NBOX], st[NBOX], sr[NBOX], sbb[NBOX], scx[NBOX], scy[NBOX];
    __shared__ float rv[128];
    __shared__ int   ri[128];
    const int b = blockIdx.y, i = blockIdx.x, t = threadIdx.x;
    if (t < NBOX) {
        float4 bx = ((const float4*)boxes)[b * NBOX + t];
        sl[t] = bx.x; st[t] = bx.y; sr[t] = bx.z; sbb[t] = bx.w;
        scx[t] = (bx.x + bx.z) * 0.5f;
        scy[t] = (bx.y + bx.w) * 0.5f;
    }
    __syncthreads();

    float l1 = sl[i], t1 = st[i], r1 = sr[i], b1 = sbb[i];
    float w1 = r1 - l1, h1 = b1 - t1;
    float area1 = w1 * h1;
    float at1   = atanf(w1 / (h1 + 1e-7f));
    float off1  = (float)i;
    float l1o = l1 + off1, t1o = t1 + off1, r1o = r1 + off1, b1o = b1 + off1;

    float best = -1e30f; int bestj = 1 << 30;
    for (int j = t; j < NBOX * 9; j += blockDim.x) {
        int jb = j / 9, a9 = j - jb * 9;
        float f = c_fs9[a9];
        float acx = floorf(scx[jb] * f) / f;
        float acy = floorf(scy[jb] * f) / f;
        float aw = c_asc_x[a9], ah = c_asc_y[a9];
        float offj = (float)jb;
        float l2 = acx - aw * 0.5f + offj, t2 = acy - ah * 0.5f + offj;
        float r2 = acx + aw * 0.5f + offj, b2 = acy + ah * 0.5f + offj;
        float w2 = r2 - l2, h2 = b2 - t2;
        float v = ciou_pre(l1o, t1o, r1o, b1o, area1, at1, l1o + r1o, t1o + b1o,
                           l2, t2, r2, b2, w2 * h2, atanf(w2 / (h2 + 1e-7f)),
                           l2 + r2, t2 + b2);
        if (v > best) { best = v; bestj = j; }
    }
    rv[t] = best; ri[t] = bestj;
    __syncthreads();
    for (int s = 64; s > 0; s >>= 1) {
        if (t < s) {
            if (rv[t + s] > rv[t] || (rv[t + s] == rv[t] && ri[t + s] < ri[t])) {
                rv[t] = rv[t + s]; ri[t] = ri[t + s];
            }
        }
        __syncthreads();
    }
    if (t == 0) {
        int k   = ri[0] % 9;
        int lev = k / 3;
        float ff = c_fs9[k];
        int col = (int)floorf(scx[i] * ff);
        int row = (int)floorf(scy[i] * ff);
        int fin = c_fsl[lev];
        int midx = (c_cum[lev] + row * fin + col) * 3 + lev;

        const float* pm = p + ((size_t)b * NANC + midx) * 25;
        float acc = focal1(pm[4]);
        int lab = labels[b * NBOX + i] - 1;
        #pragma unroll
        for (int c = 0; c < NCLS; c++) {
            float x = pm[5 + c];
            acc += softplusf(x) - ((c == lab) ? x : 0.f);
        }
        float4 pl = g_pltrb[b * NANC + midx];
        float wp = pl.z - pl.x, hp = pl.w - pl.y;
        float iou1 = ciou_pre(l1, t1, r1, b1, area1, at1, l1 + r1, t1 + b1,
                              pl.x, pl.y, pl.z, pl.w, wp * hp, atanf(wp / (hp + 1e-7f)),
                              pl.x + pl.z, pl.y + pl.w);
        acc += (2.f - area1) * (1.f - iou1);
        g_pos[b * NBOX + i] = acc;
    }
}

// ---------------- K4: deterministic fixed-tree final reduction (slim) ----------------
__global__ void k_final(float* __restrict__ out)
{
    __shared__ double sd[8];
    const int t = threadIdx.x, lane = t & 31, w = t >> 5;
    double v = 0.0;
    if (t < BATCH) v += (double)g_neg[t] * (1.0 / BATCH);
    const float4* gp = (const float4*)g_pos;            // 400 float4
    for (int i = t; i < (BATCH * NBOX) / 4; i += 256) {
        float4 q = gp[i];
        v += ((double)q.x + (double)q.y + (double)q.z + (double)q.w) * (1.0 / (BATCH * NBOX));
    }
    for (int o = 16; o > 0; o >>= 1) v += __shfl_xor_sync(0xffffffffu, v, o);
    if (lane == 0) sd[w] = v;
    __syncthreads();
    if (t < 8) {
        double x = sd[t];
        for (int o = 4; o > 0; o >>= 1) x += __shfl_xor_sync(0x000000ffu, x, o);
        if (t == 0) out[0] = (float)x;
    }
}

// ---------------- launch ----------------
extern "C" void kernel_launch(void* const* d_in, const int* in_sizes, int n_in,
                              void* d_out, int out_size)
{
    const float* p      = (const float*)d_in[0];
    const float* boxes  = (const float*)d_in[1];
    const int*   labels = (const int*)  d_in[2];
    const float* ancs   = (const float*)d_in[3];
    float*       out    = (float*)d_out;

    cudaFuncSetAttribute(k_select, cudaFuncAttributeMaxDynamicSharedMemorySize,
                         (int)(NANC * sizeof(unsigned long long)));

    const int pairs = (NANC + 1) / 2;
    dim3 g1((pairs + 255) / 256, BATCH);
    k_decode<<<g1, 256>>>(p, boxes, ancs);
    k_select<<<BATCH, 1024, NANC * sizeof(unsigned long long)>>>(p);
    dim3 g3(NBOX, BATCH);
    k_pos<<<g3, 128>>>(p, boxes, labels);
    k_final<<<1, 256>>>(out);
}

// round 6
// speedup vs baseline: 1.8952x; 1.0076x over previous
#include <cuda_runtime.h>
#include <math.h>

#define NANC   10647
#define NBOX   50
#define BATCH  32
#define NCLS   20
#define NUMNEG 1000

// ---------------- scratch (static device globals: no runtime allocation) ----------------
__device__ unsigned long long g_keys [BATCH * NANC];   // (ordered(masked)<<32)|anchor
__device__ float              g_neg  [BATCH];          // per-image l_conf_neg
__device__ __align__(16) float g_pos [BATCH * NBOX];   // per-(image,box) cls+iou+conf_pos
__device__ unsigned           g_ctr;                   // last-block counter (wraps to 0)

// ---------------- constants ----------------
__constant__ float c_asc_x[9] = {10.f/416.f,16.f/416.f,33.f/416.f,30.f/416.f,62.f/416.f,
                                 59.f/416.f,116.f/416.f,156.f/416.f,373.f/416.f};
__constant__ float c_asc_y[9] = {13.f/416.f,30.f/416.f,23.f/416.f,61.f/416.f,45.f/416.f,
                                 119.f/416.f,90.f/416.f,198.f/416.f,326.f/416.f};
__constant__ float c_fs9[9]   = {52.f,52.f,52.f,26.f,26.f,26.f,13.f,13.f,13.f};
__constant__ int   c_cum[3]   = {0, 2704, 3380};
__constant__ int   c_fsl[3]   = {52, 26, 13};

// ---------------- math helpers ----------------
// CIoU, constant-folded form. Side 1 carries area+eps and half-centers.
// areaE1 = area1 + 1e-7; cx/cy are (l+r)*0.5 / (t+b)*0.5.
__device__ __forceinline__ float ciou_f(float l1,float t1,float r1,float b1,
                                        float areaE1,float at1,float cx1,float cy1,
                                        float l2,float t2,float r2,float b2,
                                        float area2,float at2,float cx2,float cy2)
{
    float iw = fminf(r1,r2) - fmaxf(l1,l2); iw = fmaxf(iw, 0.f);
    float ih = fminf(b1,b2) - fmaxf(t1,t2); ih = fmaxf(ih, 0.f);
    float inter = iw * ih;
    float uni   = (areaE1 + area2) - inter;
    float iou   = __fdividef(inter, uni);
    float cw = fmaxf(r1,r2) - fminf(l1,l2);
    float ch = fmaxf(b1,b2) - fminf(t1,t2);
    float c2 = fmaf(cw, cw, fmaf(ch, ch, 1e-7f));
    float dx = cx1 - cx2;
    float dy = cy1 - cy2;
    float rho2 = fmaf(dx, dx, dy * dy);
    float dd = at1 - at2;
    float v  = 0.40528473456935109f * dd * dd;      // 4/pi^2
    float den = (1.0000001f - iou) + v;              // 1 - iou + v + eps
    float av  = v * __fdividef(v, den);              // alpha * v
    return iou - __fdividef(rho2, c2) - av;
}

__device__ __forceinline__ float softplusf(float x){
    return fmaxf(x, 0.f) + log1pf(expf(-fabsf(x)));
}
__device__ __forceinline__ float sigmf(float x){ return 1.f / (1.f + expf(-x)); }
__device__ __forceinline__ float focal0(float x){
    float s = sigmf(x); return softplusf(x) * 0.75f * s * s;
}
__device__ __forceinline__ float focal1(float x){
    float s = sigmf(x); float o = 1.f - s;
    return (softplusf(x) - x) * 0.25f * o * o;
}
__device__ __forceinline__ unsigned ordf(float f){
    unsigned u = __float_as_uint(f);
    return (u & 0x80000000u) ? ~u : (u | 0x80000000u);
}
__device__ __forceinline__ float fs_of(int a){
    return (a < 8112) ? 52.f : ((a < 10140) ? 26.f : 13.f);
}

struct AncReg { float l, t, r, b, area, at, cx, cy; };

__device__ __forceinline__ AncReg decode_anchor(const float* __restrict__ p,
                                                const float* __restrict__ ancs,
                                                int b, int a)
{
    const float* pp = p + ((size_t)b * NANC + a) * 25;
    float4 an = ((const float4*)ancs)[a];
    float fs = fs_of(a);
    float cx = (1.f / (1.f + expf(-pp[0]))) / fs + an.x;
    float cy = (1.f / (1.f + expf(-pp[1]))) / fs + an.y;
    float w  = expf(pp[2]) * an.z;
    float h  = expf(pp[3]) * an.w;
    AncReg R;
    R.l = cx - w * 0.5f; R.t = cy - h * 0.5f;
    R.r = cx + w * 0.5f; R.b = cy + h * 0.5f;
    R.area = w * h;
    R.at   = atanf(w / (h + 1e-7f));
    R.cx   = cx;
    R.cy   = cy;
    return R;
}

// ---------------- K1: decode + per-anchor max CIoU over boxes + OHEM keys (2 anchors/thread) ----
__global__ void k_decode(const float* __restrict__ p, const float* __restrict__ boxes,
                         const float* __restrict__ ancs)
{
    __shared__ float4 sA[NBOX];   // l,t,r,b
    __shared__ float4 sB[NBOX];   // area+eps, atan, cx, cy
    const int b = blockIdx.y;
    const int t = threadIdx.x;
    if (t < NBOX) {
        float4 bx = ((const float4*)boxes)[b * NBOX + t];
        sA[t] = bx;
        float w = bx.z - bx.x, h = bx.w - bx.y;
        sB[t] = make_float4(w * h + 1e-7f, atanf(w / (h + 1e-7f)),
                            (bx.x + bx.z) * 0.5f, (bx.y + bx.w) * 0.5f);
    }
    __syncthreads();

    int a0 = (blockIdx.x * blockDim.x + t) * 2;
    if (a0 >= NANC) return;
    const int  a1   = a0 + 1;
    const bool has1 = (a1 < NANC);

    AncReg X = decode_anchor(p, ancs, b, a0);
    AncReg Y = has1 ? decode_anchor(p, ancs, b, a1) : X;

    float mx0 = -1e30f, mx1 = -1e30f;
    #pragma unroll 2
    for (int i = 0; i < NBOX; i++) {
        float4 A  = sA[i];
        float4 Bb = sB[i];
        mx0 = fmaxf(mx0, ciou_f(A.x, A.y, A.z, A.w, Bb.x, Bb.y, Bb.z, Bb.w,
                                X.l, X.t, X.r, X.b, X.area, X.at, X.cx, X.cy));
        mx1 = fmaxf(mx1, ciou_f(A.x, A.y, A.z, A.w, Bb.x, Bb.y, Bb.z, Bb.w,
                                Y.l, Y.t, Y.r, Y.b, Y.area, Y.at, Y.cx, Y.cy));
    }
    float m0 = (mx0 < 0.5f) ? mx0 : __int_as_float(0x7f800000);
    g_keys[b * NANC + a0] = (((unsigned long long)ordf(m0)) << 32) | (unsigned)a0;
    if (has1) {
        float m1 = (mx1 < 0.5f) ? mx1 : __int_as_float(0x7f800000);
        g_keys[b * NANC + a1] = (((unsigned long long)ordf(m1)) << 32) | (unsigned)a1;
    }
}

// ---------------- K2: anchor matching (offset trick) + positive losses (no k_decode dep) -------
__global__ void k_pos(const float* __restrict__ p, const float* __restrict__ boxes,
                      const int* __restrict__ labels, const float* __restrict__ ancs)
{
    __shared__ float sl[NBOX], st[NBOX], sr[NBOX], sbb[NBOX], scx[NBOX], scy[NBOX];
    __shared__ float rv[128];
    __shared__ int   ri[128];
    const int b = blockIdx.y, i = blockIdx.x, t = threadIdx.x;
    if (t < NBOX) {
        float4 bx = ((const float4*)boxes)[b * NBOX + t];
        sl[t] = bx.x; st[t] = bx.y; sr[t] = bx.z; sbb[t] = bx.w;
        scx[t] = (bx.x + bx.z) * 0.5f;
        scy[t] = (bx.y + bx.w) * 0.5f;
    }
    __syncthreads();

    float l1 = sl[i], t1 = st[i], r1 = sr[i], b1 = sbb[i];
    float w1 = r1 - l1, h1 = b1 - t1;
    float area1  = w1 * h1;
    float areaE1 = area1 + 1e-7f;
    float at1    = atanf(w1 / (h1 + 1e-7f));
    float off1   = (float)i;
    float l1o = l1 + off1, t1o = t1 + off1, r1o = r1 + off1, b1o = b1 + off1;
    float cx1o = (l1o + r1o) * 0.5f, cy1o = (t1o + b1o) * 0.5f;

    float best = -1e30f; int bestj = 1 << 30;
    for (int j = t; j < NBOX * 9; j += blockDim.x) {
        int jb = j / 9, a9 = j - jb * 9;
        float f = c_fs9[a9];
        float acx = floorf(scx[jb] * f) / f;
        float acy = floorf(scy[jb] * f) / f;
        float aw = c_asc_x[a9], ah = c_asc_y[a9];
        float offj = (float)jb;
        float l2 = acx - aw * 0.5f + offj, t2 = acy - ah * 0.5f + offj;
        float r2 = acx + aw * 0.5f + offj, b2 = acy + ah * 0.5f + offj;
        float w2 = r2 - l2, h2 = b2 - t2;
        float v = ciou_f(l1o, t1o, r1o, b1o, areaE1, at1, cx1o, cy1o,
                         l2, t2, r2, b2, w2 * h2, atanf(w2 / (h2 + 1e-7f)),
                         (l2 + r2) * 0.5f, (t2 + b2) * 0.5f);
        if (v > best) { best = v; bestj = j; }      // ascending j -> first max within thread
    }
    rv[t] = best; ri[t] = bestj;
    __syncthreads();
    for (int s = 64; s > 0; s >>= 1) {
        if (t < s) {
            if (rv[t + s] > rv[t] || (rv[t + s] == rv[t] && ri[t + s] < ri[t])) {
                rv[t] = rv[t + s]; ri[t] = ri[t + s];
            }
        }
        __syncthreads();
    }
    if (t == 0) {
        int k   = ri[0] % 9;
        int lev = k / 3;
        float ff = c_fs9[k];
        int col = (int)floorf(scx[i] * ff);
        int row = (int)floorf(scy[i] * ff);
        int fin = c_fsl[lev];
        int midx = (c_cum[lev] + row * fin + col) * 3 + lev;

        const float* pm = p + ((size_t)b * NANC + midx) * 25;
        float acc = focal1(pm[4]);                                  // l_conf_pos
        int lab = labels[b * NBOX + i] - 1;
        #pragma unroll
        for (int c = 0; c < NCLS; c++) {                            // l_cls
            float x = pm[5 + c];
            acc += softplusf(x) - ((c == lab) ? x : 0.f);
        }
        // recompute matched anchor's decoded pred box (replaces g_pltrb)
        float4 an = ((const float4*)ancs)[midx];
        float fsm = fs_of(midx);
        float pcx = (1.f / (1.f + expf(-pm[0]))) / fsm + an.x;
        float pcy = (1.f / (1.f + expf(-pm[1]))) / fsm + an.y;
        float pw  = expf(pm[2]) * an.z;
        float ph  = expf(pm[3]) * an.w;
        float pl2 = pcx - pw * 0.5f, pt2 = pcy - ph * 0.5f;
        float pr2 = pcx + pw * 0.5f, pb2 = pcy + ph * 0.5f;
        float iou1 = ciou_f(l1, t1, r1, b1, areaE1, at1,
                            (l1 + r1) * 0.5f, (t1 + b1) * 0.5f,
                            pl2, pt2, pr2, pb2, pw * ph,
                            atanf(pw / (ph + 1e-7f)), pcx, pcy);
        acc += (2.f - area1) * (1.f - iou1);
        g_pos[b * NBOX + i] = acc;
    }
}

// ---------------- K3: radix-select + negative focal + fused final reduction -------------------
// Key layout: [63:32]=ordered float, [31:14]=0, [13:0]=anchor index. Bytes 3,2 always 0 ->
// 6 passes at shifts {56,48,40,32,8,0}, zero bytes folded into the prefix mask after pass 3.
__global__ void k_select(const float* __restrict__ p, float* __restrict__ out)
{
    extern __shared__ unsigned long long sk[];          // NANC keys (85 KB)
    __shared__ unsigned hist[256];
    __shared__ unsigned long long s_pref;
    __shared__ int s_k;
    __shared__ float s_red[32];
    __shared__ int s_last;
    __shared__ double sdd[32];

    const int b = blockIdx.x, t = threadIdx.x;
    const int lane = t & 31;
    for (int i = t; i < NANC; i += 1024) sk[i] = g_keys[b * NANC + i];
    __syncthreads();

    unsigned long long prefix = 0ull, pmask = 0ull;
    int k = NUMNEG;
    const int shifts[6] = {56, 48, 40, 32, 8, 0};

    #pragma unroll
    for (int pi = 0; pi < 6; pi++) {
        const int shift = shifts[pi];
        if (t < 256) hist[t] = 0u;
        __syncthreads();

        for (int base = 0; base < NANC; base += 1024) {
            int i = base + t;
            bool ok = false; unsigned digit = 0;
            if (i < NANC) {
                unsigned long long e = sk[i];
                ok = ((e & pmask) == prefix);
                digit = (unsigned)(e >> shift) & 255u;
            }
            unsigned bal = __ballot_sync(0xffffffffu, ok);
            if (ok) {
                unsigned same = __match_any_sync(bal, digit);
                if (lane == (__ffs(same) - 1))
                    atomicAdd(&hist[digit], __popc(same));
            }
        }
        __syncthreads();

        if (t < 32) {                                   // warp-scan over 256 bins
            int lo = t * 8;
            unsigned c[8]; int lsum = 0;
            #pragma unroll
            for (int j = 0; j < 8; j++) { c[j] = hist[lo + j]; lsum += (int)c[j]; }
            int pre = lsum;
            #pragma unroll
            for (int o = 1; o < 32; o <<= 1) {
                int n = __shfl_up_sync(0xffffffffu, pre, o);
                if (t >= o) pre += n;
            }
            int excl = pre - lsum;
            if (excl < k && k <= excl + lsum) {
                int run = excl, d = lo;
                #pragma unroll
                for (int j = 0; j < 8; j++) {
                    if (run + (int)c[j] >= k) { d = lo + j; break; }
                    run += (int)c[j];
                }
                s_pref = prefix | ((unsigned long long)(unsigned)d << shift);
                s_k    = k - run;
            }
        }
        __syncthreads();
        prefix = s_pref; k = s_k;
        pmask |= (0xFFull << shift);
        if (pi == 3) pmask |= (0xFFFFull << 16);
        __syncthreads();
    }

    float sum = 0.f;                                    // keys unique -> exactly NUMNEG pass
    for (int i = t; i < NANC; i += 1024) {
        unsigned long long e = sk[i];
        if (e <= prefix) {
            int idx = (int)(unsigned)(e & 0xffffffffu);
            sum += focal0(p[((size_t)b * NANC + idx) * 25 + 4]);
        }
    }
    for (int o = 16; o > 0; o >>= 1) sum += __shfl_xor_sync(0xffffffffu, sum, o);
    if (lane == 0) s_red[t >> 5] = sum;
    __syncthreads();
    if (t == 0) {
        float v = 0.f;
        #pragma unroll
        for (int j = 0; j < 32; j++) v += s_red[j];
        g_neg[b] = v;
        __threadfence();
        unsigned old = atomicInc(&g_ctr, BATCH - 1);    // wraps to 0 after BATCH incs
        s_last = (old == BATCH - 1);
    }
    __syncthreads();

    if (s_last) {                                       // fused final reduction (one block)
        __threadfence();                                // acquire other blocks' g_neg writes
        double v = 0.0;
        if (t < BATCH) v += (double)g_neg[t] * (1.0 / BATCH);
        const float4* gp = (const float4*)g_pos;        // 400 float4
        for (int i = t; i < (BATCH * NBOX) / 4; i += 1024) {
            float4 q = gp[i];
            v += ((double)q.x + (double)q.y + (double)q.z + (double)q.w)
                 * (1.0 / (BATCH * NBOX));
        }
        for (int o = 16; o > 0; o >>= 1) v += __shfl_xor_sync(0xffffffffu, v, o);
        if (lane == 0) sdd[t >> 5] = v;
        __syncthreads();
        if (t == 0) {
            double x = 0.0;
            #pragma unroll
            for (int j = 0; j < 32; j++) x += sdd[j];
            out[0] = (float)x;
        }
    }
}

// ---------------- launch ----------------
extern "C" void kernel_launch(void* const* d_in, const int* in_sizes, int n_in,
                              void* d_out, int out_size)
{
    const float* p      = (const float*)d_in[0];
    const float* boxes  = (const float*)d_in[1];
    const int*   labels = (const int*)  d_in[2];
    const float* ancs   = (const float*)d_in[3];
    float*       out    = (float*)d_out;

    cudaFuncSetAttribute(k_select, cudaFuncAttributeMaxDynamicSharedMemorySize,
                         (int)(NANC * sizeof(unsigned long long)));

    const int pairs = (NANC + 1) / 2;
    dim3 g1((pairs + 255) / 256, BATCH);
    k_decode<<<g1, 256>>>(p, boxes, ancs);
    dim3 g3(NBOX, BATCH);
    k_pos<<<g3, 128>>>(p, boxes, labels, ancs);
    k_select<<<BATCH, 1024, NANC * sizeof(unsigned long long)>>>(p, out);
}